// round 2
// baseline (speedup 1.0000x reference)
#include <cuda_runtime.h>
#include <cuda_bf16.h>
#include <math.h>

#define S 1024
#define B 128
#define E 10
#define H 256
#define L 4
#define G4 1024           // 4*H
#define NBPL 32           // blocks per layer
#define NBLK (NBPL * L)   // 128 persistent blocks
#define WAVES (S + L - 1) // 1027

// ---------------- device scratch (static; no allocations) ----------------
__device__ uint2  g_Wp_hi[4 * 32 * 32 * 4 * 32];   // [l][nb][kt][nt][lane] packed B frags (hi)
__device__ uint2  g_Wp_lo[4 * 32 * 32 * 4 * 32];   // (lo)
__device__ float  g_bias[4 * 32 * 32];             // permuted b_ih+b_hh per block col
__device__ float  g_w0p[32 * 32 * 10];             // layer-0 Wih (E=10) permuted per block
__device__ float  g_S[S * B * E];                  // s[t][b][e]
__device__ float  g_ssum[B * E];
__device__ float  g_C0[L * B * H];
__device__ __nv_bfloat16 g_Hhi[L * 2 * B * H];     // h state hi, double buffered
__device__ __nv_bfloat16 g_Hlo[L * 2 * B * H];     // h state lo
__device__ unsigned g_bar;

// ---------------- helpers ----------------
__device__ __forceinline__ unsigned pk(__nv_bfloat16 a, __nv_bfloat16 b) {
    __nv_bfloat162 t; t.x = a; t.y = b;
    return *reinterpret_cast<unsigned*>(&t);
}

__device__ __forceinline__ void mma16816(float c[4], const unsigned a[4],
                                         unsigned b0, unsigned b1) {
    asm volatile(
        "mma.sync.aligned.m16n8k16.row.col.f32.bf16.bf16.f32 "
        "{%0,%1,%2,%3},{%4,%5,%6,%7},{%8,%9},{%0,%1,%2,%3};"
        : "+f"(c[0]), "+f"(c[1]), "+f"(c[2]), "+f"(c[3])
        : "r"(a[0]), "r"(a[1]), "r"(a[2]), "r"(a[3]), "r"(b0), "r"(b1));
}

__device__ __forceinline__ float sigmoidf_(float x) {
    return 1.0f / (1.0f + expf(-x));
}

// ---------------- prep: pack recurrent weights into mma B-fragment order ----------------
// Block nb of layer l owns hidden cols j in [nb*8, nb*8+8), all 4 gates.
// Its 32 gate columns are permuted as n_local = nt*8 + tilecol, gate = nt.
// B matrix per block: W[k][n_local], k in [0,Kdim): k<256 -> Wih(x-part, l>=1), else Whh.
// Layer 0: Kdim=256, all Whh (E=10 x-part handled SIMT).
__global__ void k_pack(const float* __restrict__ Wihr, const float* __restrict__ Whh) {
    int idx = blockIdx.x * 256 + threadIdx.x;
    if (idx >= 4 * 32 * 32 * 4 * 32) return;
    int lane = idx & 31;
    int nt   = (idx >> 5) & 3;
    int kt   = (idx >> 7) & 31;
    int nb   = (idx >> 12) & 31;
    int l    = idx >> 17;
    if (l == 0 && kt >= 16) return;
    int ncol = lane >> 2;                 // B frag: col = lane/4
    int r    = nt * 256 + nb * 8 + ncol;  // original gate row
    int k0   = kt * 16 + (lane & 3) * 2;  // B frag: k rows (lane%4)*2 (+8)
    __nv_bfloat16 hi[4], lo[4];
#pragma unroll
    for (int q = 0; q < 4; q++) {
        int k = k0 + (q >> 1) * 8 + (q & 1);   // k0,k0+1,k0+8,k0+9
        float w;
        if (l == 0)       w = Whh[(size_t)r * H + k];
        else if (k < H)   w = Wihr[(size_t)((l - 1) * G4 + r) * H + k];
        else              w = Whh[(size_t)(l * G4 + r) * H + (k - H)];
        hi[q] = __float2bfloat16(w);
        lo[q] = __float2bfloat16(w - __bfloat162float(hi[q]));
    }
    g_Wp_hi[idx] = make_uint2(pk(hi[0], hi[1]), pk(hi[2], hi[3]));
    g_Wp_lo[idx] = make_uint2(pk(lo[0], lo[1]), pk(lo[2], lo[3]));
}

__global__ void k_pack2(const float* __restrict__ Wih0,
                        const float* __restrict__ bih,
                        const float* __restrict__ bhh) {
    int idx = blockIdx.x * 256 + threadIdx.x;
    if (idx < 4096) {
        int l = idx >> 10, nb = (idx >> 5) & 31, nl = idx & 31;
        int r = (nl >> 3) * 256 + nb * 8 + (nl & 7);
        g_bias[idx] = bih[l * G4 + r] + bhh[l * G4 + r];
    } else if (idx < 4096 + 10240) {
        int j = idx - 4096;
        int nb = j / 320, rem = j % 320, nl = rem / 10, e = rem % 10;
        int r = (nl >> 3) * 256 + nb * 8 + (nl & 7);
        g_w0p[j] = Wih0[r * E + e];
    }
}

// ---------------- prefix: s = relu((e01[x]+p01) @ f01_w.T + f01_b) ----------------
__global__ void k_embed(const int* __restrict__ x, const float* __restrict__ e01,
                        const float* __restrict__ p01, const float* __restrict__ f01w,
                        const float* __restrict__ f01b) {
    int idx = blockIdx.x * 256 + threadIdx.x;
    if (idx >= S * B) return;
    int t = idx / B;
    int tok = x[idx];
    float v[E];
#pragma unroll
    for (int e = 0; e < E; e++) v[e] = e01[tok * E + e] + p01[t * E + e];
    float* so = g_S + (size_t)idx * E;
#pragma unroll
    for (int i = 0; i < E; i++) {
        float a = f01b[i];
#pragma unroll
        for (int e = 0; e < E; e++) a += v[e] * f01w[i * E + e];
        so[i] = fmaxf(a, 0.0f);
    }
}

// deterministic reduction of s over t
__global__ void k_ssum() {
    __shared__ float red[256 * E];
    int b = blockIdx.x, tid = threadIdx.x;
    float acc[E];
#pragma unroll
    for (int e = 0; e < E; e++) acc[e] = 0.0f;
    for (int t = tid; t < S; t += 256) {
        const float* sp = g_S + ((size_t)t * B + b) * E;
#pragma unroll
        for (int e = 0; e < E; e++) acc[e] += sp[e];
    }
#pragma unroll
    for (int e = 0; e < E; e++) red[tid * E + e] = acc[e];
    __syncthreads();
    for (int s = 128; s > 0; s >>= 1) {
        if (tid < s) {
#pragma unroll
            for (int e = 0; e < E; e++) red[tid * E + e] += red[(tid + s) * E + e];
        }
        __syncthreads();
    }
    if (tid == 0) {
#pragma unroll
        for (int e = 0; e < E; e++) g_ssum[b * E + e] = red[e];
    }
}

// h0/c0 + barrier reset
__global__ void k_init(const float* __restrict__ f02w, const float* __restrict__ f02b,
                       const float* __restrict__ f03w, const float* __restrict__ f03b) {
    int idx = blockIdx.x * 256 + threadIdx.x;
    if (idx == 0) g_bar = 0;
    if (idx >= 2 * B * G4) return;
    int which = idx / (B * G4);
    int rem = idx % (B * G4);
    int b = rem / G4, r = rem % G4;
    const float* W  = which ? f03w : f02w;
    const float* bb = which ? f03b : f02b;
    float a = bb[r];
    const float* ss = g_ssum + b * E;
#pragma unroll
    for (int e = 0; e < E; e++) a += ss[e] * W[r * E + e];
    a = fmaxf(a, 0.0f);
    int l = r / H, j = r % H;
    if (which == 0) {
        int par = (l + 1) & 1;  // parity read at wave l
        __nv_bfloat16 hh = __float2bfloat16(a);
        g_Hhi[(((size_t)l * 2 + par) * B + b) * H + j] = hh;
        g_Hlo[(((size_t)l * 2 + par) * B + b) * H + j] =
            __float2bfloat16(a - __bfloat162float(hh));
    } else {
        g_C0[((size_t)l * B + b) * H + j] = a;
    }
}

// ---------------- persistent wavefront recurrent kernel ----------------
__global__ void __launch_bounds__(256) lstm_rec(float* __restrict__ out) {
    const int bid = blockIdx.x;
    const int l   = bid >> 5;
    const int nb  = bid & 31;
    const int tid = threadIdx.x;
    const int warp = tid >> 5;
    const int lane = tid & 31;

    extern __shared__ unsigned char smem[];
    uint2* Wsh = (uint2*)smem;            // [32][4][32] = 32KB
    uint2* Wsl = Wsh + 4096;              // 32KB
    float* bsm = (float*)(Wsl + 4096);    // 32
    float* w0sm = bsm + 32;               // 320 (layer 0 only)

    const int Kkt = (l == 0) ? 16 : 32;
    {
        const uint2* sh = g_Wp_hi + (size_t)(l * 32 + nb) * 4096;
        const uint2* sl = g_Wp_lo + (size_t)(l * 32 + nb) * 4096;
        for (int i = tid; i < Kkt * 128; i += 256) { Wsh[i] = sh[i]; Wsl[i] = sl[i]; }
        if (tid < 32) bsm[tid] = g_bias[(l * 32 + nb) * 32 + tid];
        if (l == 0) for (int i = tid; i < 320; i += 256) w0sm[i] = g_w0p[nb * 320 + i];
    }

    const int r0 = lane >> 2;
    const int c2 = (lane & 3) * 2;
    const int b0 = warp * 16 + r0;
    const int jj0 = nb * 8 + c2;

    float cst[4];
    cst[0] = g_C0[((size_t)l * B + b0) * H + jj0];
    cst[1] = g_C0[((size_t)l * B + b0) * H + jj0 + 1];
    cst[2] = g_C0[((size_t)l * B + b0 + 8) * H + jj0];
    cst[3] = g_C0[((size_t)l * B + b0 + 8) * H + jj0 + 1];
    __syncthreads();

    for (int wave = 0; wave < WAVES; ++wave) {
        int t = wave - l;
        if (t >= 0 && t < S) {
            const int rp = (wave + 1) & 1;  // parity written last wave
            const __nv_bfloat16* HhiOwn = g_Hhi + ((size_t)(l * 2 + rp) * B) * H;
            const __nv_bfloat16* HloOwn = g_Hlo + ((size_t)(l * 2 + rp) * B) * H;
            const __nv_bfloat16* HhiIn =
                (l > 0) ? g_Hhi + ((size_t)((l - 1) * 2 + rp) * B) * H : HhiOwn;
            const __nv_bfloat16* HloIn =
                (l > 0) ? g_Hlo + ((size_t)((l - 1) * 2 + rp) * B) * H : HloOwn;

            float acc[4][4];
#pragma unroll
            for (int nt = 0; nt < 4; nt++) {
#pragma unroll
                for (int rg = 0; rg < 4; rg++)
                    acc[nt][rg] = bsm[nt * 8 + c2 + (rg & 1)];
            }

#pragma unroll 4
            for (int kt = 0; kt < Kkt; ++kt) {
                const __nv_bfloat16 *Ah, *Al;
                int kb;
                if (l > 0 && kt < 16) { Ah = HhiIn; Al = HloIn; kb = kt * 16; }
                else { Ah = HhiOwn; Al = HloOwn; kb = (l > 0 ? (kt - 16) : kt) * 16; }
                const int ofs = b0 * H + kb + c2;
                unsigned a[4], al[4];
                a[0]  = *(const unsigned*)(Ah + ofs);
                a[1]  = *(const unsigned*)(Ah + ofs + 8 * H);
                a[2]  = *(const unsigned*)(Ah + ofs + 8);
                a[3]  = *(const unsigned*)(Ah + ofs + 8 * H + 8);
                al[0] = *(const unsigned*)(Al + ofs);
                al[1] = *(const unsigned*)(Al + ofs + 8 * H);
                al[2] = *(const unsigned*)(Al + ofs + 8);
                al[3] = *(const unsigned*)(Al + ofs + 8 * H + 8);
#pragma unroll
                for (int nt = 0; nt < 4; nt++) {
                    uint2 wh = Wsh[kt * 128 + nt * 32 + lane];
                    uint2 wl = Wsl[kt * 128 + nt * 32 + lane];
                    mma16816(acc[nt], a,  wh.x, wh.y);   // Ahi * Whi
                    mma16816(acc[nt], a,  wl.x, wl.y);   // Ahi * Wlo
                    mma16816(acc[nt], al, wh.x, wh.y);   // Alo * Whi
                }
            }

            if (l == 0) {  // E=10 input contribution, SIMT
                float sv0[E], sv1[E];
                const float* sp = g_S + ((size_t)t * B + b0) * E;
#pragma unroll
                for (int e = 0; e < E; e++) { sv0[e] = sp[e]; sv1[e] = sp[8 * E + e]; }
#pragma unroll
                for (int nt = 0; nt < 4; nt++) {
                    const float* wA = w0sm + (nt * 8 + c2) * E;
                    const float* wB = wA + E;
#pragma unroll
                    for (int e = 0; e < E; e++) {
                        acc[nt][0] += sv0[e] * wA[e];
                        acc[nt][1] += sv0[e] * wB[e];
                        acc[nt][2] += sv1[e] * wA[e];
                        acc[nt][3] += sv1[e] * wB[e];
                    }
                }
            }

            const int wp = wave & 1;
            __nv_bfloat16* Ohi = g_Hhi + ((size_t)(l * 2 + wp) * B) * H;
            __nv_bfloat16* Olo = g_Hlo + ((size_t)(l * 2 + wp) * B) * H;
#pragma unroll
            for (int rg = 0; rg < 4; rg++) {
                float iv = sigmoidf_(acc[0][rg]);
                float fv = sigmoidf_(acc[1][rg]);
                float gv = tanhf(acc[2][rg]);
                float ov = sigmoidf_(acc[3][rg]);
                float cv = fv * cst[rg] + iv * gv;
                cst[rg] = cv;
                float hv = ov * tanhf(cv);
                int bb = b0 + (rg >> 1) * 8;
                int jj = jj0 + (rg & 1);
                __nv_bfloat16 hh = __float2bfloat16(hv);
                Ohi[bb * H + jj] = hh;
                Olo[bb * H + jj] = __float2bfloat16(hv - __bfloat162float(hh));
                if (t == S - 1) out[bb * G4 + l * H + jj] = hv;
            }
        }

        // grid barrier (all 128 blocks co-resident on 148 SMs)
        __syncthreads();
        if (tid == 0) {
            __threadfence();
            atomicAdd(&g_bar, 1u);
            unsigned target = (unsigned)(wave + 1) * NBLK;
            while (*(volatile unsigned*)&g_bar < target) __nanosleep(32);
            __threadfence();
        }
        __syncthreads();
    }
}

// ---------------- launch ----------------
extern "C" void kernel_launch(void* const* d_in, const int* in_sizes, int n_in,
                              void* d_out, int out_size) {
    const int*   x    = (const int*)d_in[0];
    const float* e01  = (const float*)d_in[1];
    const float* p01  = (const float*)d_in[2];
    const float* f01w = (const float*)d_in[3];
    const float* f01b = (const float*)d_in[4];
    const float* f02w = (const float*)d_in[5];
    const float* f02b = (const float*)d_in[6];
    const float* f03w = (const float*)d_in[7];
    const float* f03b = (const float*)d_in[8];
    const float* Wih0 = (const float*)d_in[9];
    const float* Wihr = (const float*)d_in[10];
    const float* Whh  = (const float*)d_in[11];
    const float* bih  = (const float*)d_in[12];
    const float* bhh  = (const float*)d_in[13];
    float* out = (float*)d_out;

    k_pack<<<(4 * 32 * 32 * 4 * 32 + 255) / 256, 256>>>(Wihr, Whh);
    k_pack2<<<(4096 + 10240 + 255) / 256, 256>>>(Wih0, bih, bhh);
    k_embed<<<(S * B + 255) / 256, 256>>>(x, e01, p01, f01w, f01b);
    k_ssum<<<B, 256>>>();
    k_init<<<(2 * B * G4 + 255) / 256, 256>>>(f02w, f02b, f03w, f03b);

    const int smem_bytes = 4096 * 8 * 2 + (32 + 320) * 4;  // 66944
    cudaFuncSetAttribute(lstm_rec, cudaFuncAttributeMaxDynamicSharedMemorySize,
                         smem_bytes);
    lstm_rec<<<NBLK, 256, smem_bytes>>>(out);
}

// round 3
// speedup vs baseline: 1.0037x; 1.0037x over previous
#include <cuda_runtime.h>
#include <cuda_bf16.h>
#include <math.h>

#define S 1024
#define B 128
#define E 10
#define H 256
#define L 4
#define G4 1024           // 4*H
#define NBPL 32           // blocks per layer
#define NBLK (NBPL * L)   // 128 persistent blocks
#define WAVES (S + L - 1) // 1027

// ---------------- device scratch (static; no allocations) ----------------
__device__ uint2  g_Wp_hi[4 * 32 * 32 * 4 * 32];   // [l][nb][kt][nt][lane] packed B frags (hi)
__device__ uint2  g_Wp_lo[4 * 32 * 32 * 4 * 32];   // (lo)
__device__ float  g_bias[4 * 32 * 32];             // permuted b_ih+b_hh per block col
__device__ float  g_w0p[32 * 32 * 10];             // layer-0 Wih (E=10) permuted per block
__device__ float  g_S[S * B * E];                  // s[t][b][e]
__device__ float  g_ssum[B * E];
__device__ float  g_C0[L * B * H];
__device__ __nv_bfloat16 g_Hhi[L * 2 * B * H];     // h state hi, double buffered
__device__ __nv_bfloat16 g_Hlo[L * 2 * B * H];     // h state lo
__device__ unsigned g_bar;

// ---------------- helpers ----------------
__device__ __forceinline__ unsigned pk(__nv_bfloat16 a, __nv_bfloat16 b) {
    __nv_bfloat162 t; t.x = a; t.y = b;
    return *reinterpret_cast<unsigned*>(&t);
}

__device__ __forceinline__ void mma16816(float c[4], const unsigned a[4],
                                         unsigned b0, unsigned b1) {
    asm volatile(
        "mma.sync.aligned.m16n8k16.row.col.f32.bf16.bf16.f32 "
        "{%0,%1,%2,%3},{%4,%5,%6,%7},{%8,%9},{%0,%1,%2,%3};"
        : "+f"(c[0]), "+f"(c[1]), "+f"(c[2]), "+f"(c[3])
        : "r"(a[0]), "r"(a[1]), "r"(a[2]), "r"(a[3]), "r"(b0), "r"(b1));
}

__device__ __forceinline__ float sigmoidf_(float x) {
    return 1.0f / (1.0f + expf(-x));
}

// ---------------- prep: pack recurrent weights into mma B-fragment order ----------------
// Block nb of layer l owns hidden cols j in [nb*8, nb*8+8), all 4 gates.
// Its 32 gate columns are permuted as n_local = nt*8 + tilecol, gate = nt.
// B matrix per block: W[k][n_local], k in [0,Kdim): k<256 -> Wih(x-part, l>=1), else Whh.
// Layer 0: Kdim=256, all Whh (E=10 x-part handled SIMT).
__global__ void k_pack(const float* __restrict__ Wihr, const float* __restrict__ Whh) {
    int idx = blockIdx.x * 256 + threadIdx.x;
    if (idx >= 4 * 32 * 32 * 4 * 32) return;
    int lane = idx & 31;
    int nt   = (idx >> 5) & 3;
    int kt   = (idx >> 7) & 31;
    int nb   = (idx >> 12) & 31;
    int l    = idx >> 17;
    if (l == 0 && kt >= 16) return;
    int ncol = lane >> 2;                 // B frag: col = lane/4
    int r    = nt * 256 + nb * 8 + ncol;  // original gate row
    int k0   = kt * 16 + (lane & 3) * 2;  // B frag: k rows (lane%4)*2 (+8)
    __nv_bfloat16 hi[4], lo[4];
#pragma unroll
    for (int q = 0; q < 4; q++) {
        int k = k0 + (q >> 1) * 8 + (q & 1);   // k0,k0+1,k0+8,k0+9
        float w;
        if (l == 0)       w = Whh[(size_t)r * H + k];
        else if (k < H)   w = Wihr[(size_t)((l - 1) * G4 + r) * H + k];
        else              w = Whh[(size_t)(l * G4 + r) * H + (k - H)];
        hi[q] = __float2bfloat16(w);
        lo[q] = __float2bfloat16(w - __bfloat162float(hi[q]));
    }
    g_Wp_hi[idx] = make_uint2(pk(hi[0], hi[1]), pk(hi[2], hi[3]));
    g_Wp_lo[idx] = make_uint2(pk(lo[0], lo[1]), pk(lo[2], lo[3]));
}

__global__ void k_pack2(const float* __restrict__ Wih0,
                        const float* __restrict__ bih,
                        const float* __restrict__ bhh) {
    int idx = blockIdx.x * 256 + threadIdx.x;
    if (idx < 4096) {
        int l = idx >> 10, nb = (idx >> 5) & 31, nl = idx & 31;
        int r = (nl >> 3) * 256 + nb * 8 + (nl & 7);
        g_bias[idx] = bih[l * G4 + r] + bhh[l * G4 + r];
    } else if (idx < 4096 + 10240) {
        int j = idx - 4096;
        int nb = j / 320, rem = j % 320, nl = rem / 10, e = rem % 10;
        int r = (nl >> 3) * 256 + nb * 8 + (nl & 7);
        g_w0p[j] = Wih0[r * E + e];
    }
}

// ---------------- prefix: s = relu((e01[x]+p01) @ f01_w.T + f01_b) ----------------
__global__ void k_embed(const int* __restrict__ x, const float* __restrict__ e01,
                        const float* __restrict__ p01, const float* __restrict__ f01w,
                        const float* __restrict__ f01b) {
    int idx = blockIdx.x * 256 + threadIdx.x;
    if (idx >= S * B) return;
    int t = idx / B;
    int tok = x[idx];
    float v[E];
#pragma unroll
    for (int e = 0; e < E; e++) v[e] = e01[tok * E + e] + p01[t * E + e];
    float* so = g_S + (size_t)idx * E;
#pragma unroll
    for (int i = 0; i < E; i++) {
        float a = f01b[i];
#pragma unroll
        for (int e = 0; e < E; e++) a += v[e] * f01w[i * E + e];
        so[i] = fmaxf(a, 0.0f);
    }
}

// deterministic reduction of s over t
__global__ void k_ssum() {
    __shared__ float red[256 * E];
    int b = blockIdx.x, tid = threadIdx.x;
    float acc[E];
#pragma unroll
    for (int e = 0; e < E; e++) acc[e] = 0.0f;
    for (int t = tid; t < S; t += 256) {
        const float* sp = g_S + ((size_t)t * B + b) * E;
#pragma unroll
        for (int e = 0; e < E; e++) acc[e] += sp[e];
    }
#pragma unroll
    for (int e = 0; e < E; e++) red[tid * E + e] = acc[e];
    __syncthreads();
    for (int s = 128; s > 0; s >>= 1) {
        if (tid < s) {
#pragma unroll
            for (int e = 0; e < E; e++) red[tid * E + e] += red[(tid + s) * E + e];
        }
        __syncthreads();
    }
    if (tid == 0) {
#pragma unroll
        for (int e = 0; e < E; e++) g_ssum[b * E + e] = red[e];
    }
}

// h0/c0 + barrier reset
__global__ void k_init(const float* __restrict__ f02w, const float* __restrict__ f02b,
                       const float* __restrict__ f03w, const float* __restrict__ f03b) {
    int idx = blockIdx.x * 256 + threadIdx.x;
    if (idx == 0) g_bar = 0;
    if (idx >= 2 * B * G4) return;
    int which = idx / (B * G4);
    int rem = idx % (B * G4);
    int b = rem / G4, r = rem % G4;
    const float* W  = which ? f03w : f02w;
    const float* bb = which ? f03b : f02b;
    float a = bb[r];
    const float* ss = g_ssum + b * E;
#pragma unroll
    for (int e = 0; e < E; e++) a += ss[e] * W[r * E + e];
    a = fmaxf(a, 0.0f);
    int l = r / H, j = r % H;
    if (which == 0) {
        int par = (l + 1) & 1;  // parity read at wave l
        __nv_bfloat16 hh = __float2bfloat16(a);
        g_Hhi[(((size_t)l * 2 + par) * B + b) * H + j] = hh;
        g_Hlo[(((size_t)l * 2 + par) * B + b) * H + j] =
            __float2bfloat16(a - __bfloat162float(hh));
    } else {
        g_C0[((size_t)l * B + b) * H + j] = a;
    }
}

// ---------------- persistent wavefront recurrent kernel ----------------
__global__ void __launch_bounds__(256) lstm_rec(float* __restrict__ out) {
    const int bid = blockIdx.x;
    const int l   = bid >> 5;
    const int nb  = bid & 31;
    const int tid = threadIdx.x;
    const int warp = tid >> 5;
    const int lane = tid & 31;

    extern __shared__ unsigned char smem[];
    uint2* Wsh = (uint2*)smem;            // [32][4][32] = 32KB
    uint2* Wsl = Wsh + 4096;              // 32KB
    float* bsm = (float*)(Wsl + 4096);    // 32
    float* w0sm = bsm + 32;               // 320 (layer 0 only)

    const int Kkt = (l == 0) ? 16 : 32;
    {
        const uint2* sh = g_Wp_hi + (size_t)(l * 32 + nb) * 4096;
        const uint2* sl = g_Wp_lo + (size_t)(l * 32 + nb) * 4096;
        for (int i = tid; i < Kkt * 128; i += 256) { Wsh[i] = sh[i]; Wsl[i] = sl[i]; }
        if (tid < 32) bsm[tid] = g_bias[(l * 32 + nb) * 32 + tid];
        if (l == 0) for (int i = tid; i < 320; i += 256) w0sm[i] = g_w0p[nb * 320 + i];
    }

    const int r0 = lane >> 2;
    const int c2 = (lane & 3) * 2;
    const int b0 = warp * 16 + r0;
    const int jj0 = nb * 8 + c2;

    float cst[4];
    cst[0] = g_C0[((size_t)l * B + b0) * H + jj0];
    cst[1] = g_C0[((size_t)l * B + b0) * H + jj0 + 1];
    cst[2] = g_C0[((size_t)l * B + b0 + 8) * H + jj0];
    cst[3] = g_C0[((size_t)l * B + b0 + 8) * H + jj0 + 1];
    __syncthreads();

    for (int wave = 0; wave < WAVES; ++wave) {
        int t = wave - l;
        if (t >= 0 && t < S) {
            const int rp = (wave + 1) & 1;  // parity written last wave
            const __nv_bfloat16* HhiOwn = g_Hhi + ((size_t)(l * 2 + rp) * B) * H;
            const __nv_bfloat16* HloOwn = g_Hlo + ((size_t)(l * 2 + rp) * B) * H;
            const __nv_bfloat16* HhiIn =
                (l > 0) ? g_Hhi + ((size_t)((l - 1) * 2 + rp) * B) * H : HhiOwn;
            const __nv_bfloat16* HloIn =
                (l > 0) ? g_Hlo + ((size_t)((l - 1) * 2 + rp) * B) * H : HloOwn;

            float acc[4][4];
#pragma unroll
            for (int nt = 0; nt < 4; nt++) {
#pragma unroll
                for (int rg = 0; rg < 4; rg++)
                    acc[nt][rg] = bsm[nt * 8 + c2 + (rg & 1)];
            }

#pragma unroll 4
            for (int kt = 0; kt < Kkt; ++kt) {
                const __nv_bfloat16 *Ah, *Al;
                int kb;
                if (l > 0 && kt < 16) { Ah = HhiIn; Al = HloIn; kb = kt * 16; }
                else { Ah = HhiOwn; Al = HloOwn; kb = (l > 0 ? (kt - 16) : kt) * 16; }
                const int ofs = b0 * H + kb + c2;
                unsigned a[4], al[4];
                a[0]  = *(const unsigned*)(Ah + ofs);
                a[1]  = *(const unsigned*)(Ah + ofs + 8 * H);
                a[2]  = *(const unsigned*)(Ah + ofs + 8);
                a[3]  = *(const unsigned*)(Ah + ofs + 8 * H + 8);
                al[0] = *(const unsigned*)(Al + ofs);
                al[1] = *(const unsigned*)(Al + ofs + 8 * H);
                al[2] = *(const unsigned*)(Al + ofs + 8);
                al[3] = *(const unsigned*)(Al + ofs + 8 * H + 8);
#pragma unroll
                for (int nt = 0; nt < 4; nt++) {
                    uint2 wh = Wsh[kt * 128 + nt * 32 + lane];
                    uint2 wl = Wsl[kt * 128 + nt * 32 + lane];
                    mma16816(acc[nt], a,  wh.x, wh.y);   // Ahi * Whi
                    mma16816(acc[nt], a,  wl.x, wl.y);   // Ahi * Wlo
                    mma16816(acc[nt], al, wh.x, wh.y);   // Alo * Whi
                }
            }

            if (l == 0) {  // E=10 input contribution, SIMT
                float sv0[E], sv1[E];
                const float* sp = g_S + ((size_t)t * B + b0) * E;
#pragma unroll
                for (int e = 0; e < E; e++) { sv0[e] = sp[e]; sv1[e] = sp[8 * E + e]; }
#pragma unroll
                for (int nt = 0; nt < 4; nt++) {
                    const float* wA = w0sm + (nt * 8 + c2) * E;
                    const float* wB = wA + E;
#pragma unroll
                    for (int e = 0; e < E; e++) {
                        acc[nt][0] += sv0[e] * wA[e];
                        acc[nt][1] += sv0[e] * wB[e];
                        acc[nt][2] += sv1[e] * wA[e];
                        acc[nt][3] += sv1[e] * wB[e];
                    }
                }
            }

            const int wp = wave & 1;
            __nv_bfloat16* Ohi = g_Hhi + ((size_t)(l * 2 + wp) * B) * H;
            __nv_bfloat16* Olo = g_Hlo + ((size_t)(l * 2 + wp) * B) * H;
#pragma unroll
            for (int rg = 0; rg < 4; rg++) {
                float iv = sigmoidf_(acc[0][rg]);
                float fv = sigmoidf_(acc[1][rg]);
                float gv = tanhf(acc[2][rg]);
                float ov = sigmoidf_(acc[3][rg]);
                float cv = fv * cst[rg] + iv * gv;
                cst[rg] = cv;
                float hv = ov * tanhf(cv);
                int bb = b0 + (rg >> 1) * 8;
                int jj = jj0 + (rg & 1);
                __nv_bfloat16 hh = __float2bfloat16(hv);
                Ohi[bb * H + jj] = hh;
                Olo[bb * H + jj] = __float2bfloat16(hv - __bfloat162float(hh));
                if (t == S - 1) out[bb * G4 + l * H + jj] = hv;
            }
        }

        // grid barrier (all 128 blocks co-resident on 148 SMs)
        __syncthreads();
        if (tid == 0) {
            __threadfence();
            atomicAdd(&g_bar, 1u);
            unsigned target = (unsigned)(wave + 1) * NBLK;
            while (*(volatile unsigned*)&g_bar < target) __nanosleep(32);
            __threadfence();
        }
        __syncthreads();
    }
}

// ---------------- launch ----------------
extern "C" void kernel_launch(void* const* d_in, const int* in_sizes, int n_in,
                              void* d_out, int out_size) {
    const int*   x    = (const int*)d_in[0];
    const float* e01  = (const float*)d_in[1];
    const float* p01  = (const float*)d_in[2];
    const float* f01w = (const float*)d_in[3];
    const float* f01b = (const float*)d_in[4];
    const float* f02w = (const float*)d_in[5];
    const float* f02b = (const float*)d_in[6];
    const float* f03w = (const float*)d_in[7];
    const float* f03b = (const float*)d_in[8];
    const float* Wih0 = (const float*)d_in[9];
    const float* Wihr = (const float*)d_in[10];
    const float* Whh  = (const float*)d_in[11];
    const float* bih  = (const float*)d_in[12];
    const float* bhh  = (const float*)d_in[13];
    float* out = (float*)d_out;

    k_pack<<<(4 * 32 * 32 * 4 * 32 + 255) / 256, 256>>>(Wihr, Whh);
    k_pack2<<<(4096 + 10240 + 255) / 256, 256>>>(Wih0, bih, bhh);
    k_embed<<<(S * B + 255) / 256, 256>>>(x, e01, p01, f01w, f01b);
    k_ssum<<<B, 256>>>();
    k_init<<<(2 * B * G4 + 255) / 256, 256>>>(f02w, f02b, f03w, f03b);

    const int smem_bytes = 4096 * 8 * 2 + (32 + 320) * 4;  // 66944
    cudaFuncSetAttribute(lstm_rec, cudaFuncAttributeMaxDynamicSharedMemorySize,
                         smem_bytes);
    lstm_rec<<<NBLK, 256, smem_bytes>>>(out);
}

// round 4
// speedup vs baseline: 1.4629x; 1.4575x over previous
#include <cuda_runtime.h>
#include <cuda_bf16.h>
#include <math.h>

#define S 1024
#define B 128
#define E 10
#define H 256
#define L 4
#define G4 1024           // 4*H
#define NBPL 32           // blocks per layer
#define NBLK (NBPL * L)   // 128 persistent blocks

// ---------------- device scratch (static; no allocations) ----------------
// merged weight fragments: [l][nb][kt][nt][lane] = uint4(whi.x, whi.y, wlo.x, wlo.y)
__device__ __align__(16) uint4  g_Wp[4 * 32 * 32 * 4 * 32];
__device__ float  g_bias[4 * 32 * 32];
__device__ float  g_w0p[32 * 32 * 10];
__device__ float  g_S[S * B * E];
__device__ float  g_C0[L * B * H];
__device__ __align__(16) __nv_bfloat16 g_Hhi[L * 2 * B * H];  // [l][parity][b][jperm]
__device__ __align__(16) __nv_bfloat16 g_Hlo[L * 2 * B * H];
__device__ int g_cnt[L];   // per-layer completed-block-step counters

// ---------------- helpers ----------------
__device__ __host__ __forceinline__ int permk(int j) {
    // within each 16-wide tile reorder [0,1,8,9,2,3,10,11,4,5,12,13,6,7,14,15]
    int tile = j >> 4, q = j & 15;
    int n = (q & 1) | (((q >> 3) & 1) << 1) | ((q & 6) << 1);
    return tile * 16 + n;
}

__device__ __forceinline__ unsigned pk(__nv_bfloat16 a, __nv_bfloat16 b) {
    __nv_bfloat162 t; t.x = a; t.y = b;
    return *reinterpret_cast<unsigned*>(&t);
}

__device__ __forceinline__ void mma16816(float c[4], const unsigned a[4],
                                         unsigned b0, unsigned b1) {
    asm volatile(
        "mma.sync.aligned.m16n8k16.row.col.f32.bf16.bf16.f32 "
        "{%0,%1,%2,%3},{%4,%5,%6,%7},{%8,%9},{%0,%1,%2,%3};"
        : "+f"(c[0]), "+f"(c[1]), "+f"(c[2]), "+f"(c[3])
        : "r"(a[0]), "r"(a[1]), "r"(a[2]), "r"(a[3]), "r"(b0), "r"(b1));
}

__device__ __forceinline__ float fsig(float x) {
    return __fdividef(1.0f, 1.0f + __expf(-x));
}
__device__ __forceinline__ float ftanh(float x) {
    return 1.0f - __fdividef(2.0f, __expf(2.0f * x) + 1.0f);
}

// ---------------- prep 1: pack weights + biases + layer0 Wih ----------------
__global__ void k_prep(const float* __restrict__ Wih0, const float* __restrict__ Wihr,
                       const float* __restrict__ Whh,  const float* __restrict__ bih,
                       const float* __restrict__ bhh) {
    int idx = blockIdx.x * 256 + threadIdx.x;
    if (idx < 4 * 32 * 32 * 4 * 32) {
        int lane = idx & 31;
        int nt   = (idx >> 5) & 3;
        int kt   = (idx >> 7) & 31;
        int nb   = (idx >> 12) & 31;
        int l    = idx >> 17;
        if (l == 0 && kt >= 16) return;
        int ncol = lane >> 2;
        int r    = nt * 256 + nb * 8 + ncol;
        int k0   = kt * 16 + (lane & 3) * 2;
        __nv_bfloat16 hi[4], lo[4];
#pragma unroll
        for (int q = 0; q < 4; q++) {
            int k = k0 + (q >> 1) * 8 + (q & 1);   // k0,k0+1,k0+8,k0+9
            float w;
            if (l == 0)       w = Whh[(size_t)r * H + k];
            else if (k < H)   w = Wihr[(size_t)((l - 1) * G4 + r) * H + k];
            else              w = Whh[(size_t)(l * G4 + r) * H + (k - H)];
            hi[q] = __float2bfloat16(w);
            lo[q] = __float2bfloat16(w - __bfloat162float(hi[q]));
        }
        g_Wp[idx] = make_uint4(pk(hi[0], hi[1]), pk(hi[2], hi[3]),
                               pk(lo[0], lo[1]), pk(lo[2], lo[3]));
    } else {
        int j = idx - 4 * 32 * 32 * 4 * 32;
        if (j < 4096) {
            int l = j >> 10, nb = (j >> 5) & 31, nl = j & 31;
            int r = (nl >> 3) * 256 + nb * 8 + (nl & 7);
            g_bias[j] = bih[l * G4 + r] + bhh[l * G4 + r];
        } else if (j < 4096 + 10240) {
            int jj = j - 4096;
            int nb = jj / 320, rem = jj % 320, nl = rem / 10, e = rem % 10;
            int r = (nl >> 3) * 256 + nb * 8 + (nl & 7);
            g_w0p[jj] = Wih0[r * E + e];
        }
    }
}

// ---------------- prep 2: s = relu((e01[x]+p01) @ f01_w.T + f01_b) ----------------
__global__ void k_embed(const int* __restrict__ x, const float* __restrict__ e01,
                        const float* __restrict__ p01, const float* __restrict__ f01w,
                        const float* __restrict__ f01b) {
    int idx = blockIdx.x * 256 + threadIdx.x;
    if (idx >= S * B) return;
    int t = idx / B;
    int tok = x[idx];
    float v[E];
#pragma unroll
    for (int e = 0; e < E; e++) v[e] = e01[tok * E + e] + p01[t * E + e];
    float* so = g_S + (size_t)idx * E;
#pragma unroll
    for (int i = 0; i < E; i++) {
        float a = f01b[i];
#pragma unroll
        for (int e = 0; e < E; e++) a += v[e] * f01w[i * E + e];
        so[i] = fmaxf(a, 0.0f);
    }
}

// ---------------- prep 3: ssum + h0/c0 + counter reset (fused) ----------------
__global__ void k_ssum_init(const float* __restrict__ f02w, const float* __restrict__ f02b,
                            const float* __restrict__ f03w, const float* __restrict__ f03b) {
    __shared__ float red[256 * E];
    __shared__ float ss[E];
    int b = blockIdx.x, tid = threadIdx.x;
    float acc[E];
#pragma unroll
    for (int e = 0; e < E; e++) acc[e] = 0.0f;
    for (int t = tid; t < S; t += 256) {
        const float* sp = g_S + ((size_t)t * B + b) * E;
#pragma unroll
        for (int e = 0; e < E; e++) acc[e] += sp[e];
    }
#pragma unroll
    for (int e = 0; e < E; e++) red[tid * E + e] = acc[e];
    __syncthreads();
    for (int s = 128; s > 0; s >>= 1) {
        if (tid < s) {
#pragma unroll
            for (int e = 0; e < E; e++) red[tid * E + e] += red[(tid + s) * E + e];
        }
        __syncthreads();
    }
    if (tid < E) ss[tid] = red[tid];
    if (b == 0 && tid < L) g_cnt[tid] = 0;
    __syncthreads();
    // 1024 h rows + 1024 c rows, 256 threads x 4 each
#pragma unroll
    for (int i = 0; i < 4; i++) {
        int r = tid + i * 256;           // gate row 0..1023
        float ah = f02b[r], ac = f03b[r];
#pragma unroll
        for (int e = 0; e < E; e++) {
            ah += ss[e] * f02w[r * E + e];
            ac += ss[e] * f03w[r * E + e];
        }
        ah = fmaxf(ah, 0.0f);
        ac = fmaxf(ac, 0.0f);
        int l = r >> 8, j = r & 255;
        int jp = permk(j);
        __nv_bfloat16 hh = __float2bfloat16(ah);
        // initial h = "step -1" output -> parity 1
        g_Hhi[(((size_t)l * 2 + 1) * B + b) * H + jp] = hh;
        g_Hlo[(((size_t)l * 2 + 1) * B + b) * H + jp] =
            __float2bfloat16(ah - __bfloat162float(hh));
        g_C0[((size_t)l * B + b) * H + j] = ac;
    }
}

// ---------------- persistent recurrent kernel, decoupled per-layer pipeline ----------------
__global__ void __launch_bounds__(256, 1) lstm_rec(float* __restrict__ out) {
    const int bid = blockIdx.x;
    const int l   = bid >> 5;
    const int nb  = bid & 31;
    const int tid = threadIdx.x;
    const int warp = tid >> 5;
    const int lane = tid & 31;

    extern __shared__ unsigned char smem[];
    uint4* Wsm  = (uint4*)smem;                 // [32][4][32] uint4 = 64KB
    float* bsm  = (float*)(Wsm + 4096);         // 32
    float* w0sm = bsm + 32;                     // 320 (layer 0 only)

    const int Kkt = (l == 0) ? 16 : 32;
    {
        const uint4* src = g_Wp + (size_t)(l * 32 + nb) * 4096;
        for (int i = tid; i < Kkt * 128; i += 256) Wsm[i] = src[i];
        if (tid < 32) bsm[tid] = g_bias[(l * 32 + nb) * 32 + tid];
        if (l == 0) for (int i = tid; i < 320; i += 256) w0sm[i] = g_w0p[nb * 320 + i];
    }

    const int qd  = lane & 3;
    const int r0  = lane >> 2;
    const int c2  = qd * 2;
    const int b0  = warp * 16 + r0;
    const int jj0 = nb * 8 + c2;
    const int jp0 = permk(jj0);                 // even -> even, pair stays adjacent

    float cst[4];
    cst[0] = g_C0[((size_t)l * B + b0) * H + jj0];
    cst[1] = g_C0[((size_t)l * B + b0) * H + jj0 + 1];
    cst[2] = g_C0[((size_t)l * B + b0 + 8) * H + jj0];
    cst[3] = g_C0[((size_t)l * B + b0 + 8) * H + jj0 + 1];
    __syncthreads();

    volatile int* vcnt = g_cnt;
    // u64 views of h buffers; row = 64 u64 (H*2B/8)
    const unsigned long long* Hhi64 = (const unsigned long long*)g_Hhi;
    const unsigned long long* Hlo64 = (const unsigned long long*)g_Hlo;

    for (int t = 0; t < S; ++t) {
        if (tid == 0) {
            const int t32 = 32 * t;
            if (t > 0)            while (vcnt[l]     < t32)      { }
            if (l > 0)            while (vcnt[l - 1] < t32 + 32) { }
            if (l < 3 && t >= 2)  while (vcnt[l + 1] < t32 - 32) { }
            __threadfence();
        }
        __syncthreads();

        const int pOwn = (t + 1) & 1;   // own h from step t-1
        const int pIn  = t & 1;         // layer l-1 h from step t
        const size_t baseOwn = ((size_t)(l * 2 + pOwn) * B) * 64;
        const size_t baseIn  = (l > 0) ? ((size_t)((l - 1) * 2 + pIn) * B) * 64 : baseOwn;

        float acc[4][4];
#pragma unroll
        for (int nt = 0; nt < 4; nt++) {
#pragma unroll
            for (int rg = 0; rg < 4; rg++)
                acc[nt][rg] = bsm[nt * 8 + c2 + (rg & 1)];
        }

#pragma unroll 4
        for (int kt = 0; kt < Kkt; ++kt) {
            size_t base; int kt16;
            if (l > 0 && kt < 16) { base = baseIn;  kt16 = kt; }
            else                  { base = baseOwn; kt16 = (l > 0) ? kt - 16 : kt; }
            const size_t o0 = base + (size_t)b0 * 64 + kt16 * 4 + qd;
            unsigned long long vh0 = __ldcg(Hhi64 + o0);
            unsigned long long vh1 = __ldcg(Hhi64 + o0 + 8 * 64);
            unsigned long long vl0 = __ldcg(Hlo64 + o0);
            unsigned long long vl1 = __ldcg(Hlo64 + o0 + 8 * 64);
            unsigned a[4], al[4];
            a[0]  = (unsigned)vh0;  a[2] = (unsigned)(vh0 >> 32);
            a[1]  = (unsigned)vh1;  a[3] = (unsigned)(vh1 >> 32);
            al[0] = (unsigned)vl0;  al[2] = (unsigned)(vl0 >> 32);
            al[1] = (unsigned)vl1;  al[3] = (unsigned)(vl1 >> 32);
#pragma unroll
            for (int nt = 0; nt < 4; nt++) {
                uint4 w = Wsm[kt * 128 + nt * 32 + lane];
                mma16816(acc[nt], a,  w.x, w.y);   // Ahi * Whi
                mma16816(acc[nt], al, w.x, w.y);   // Alo * Whi
                mma16816(acc[nt], a,  w.z, w.w);   // Ahi * Wlo
            }
        }

        if (l == 0) {  // E=10 input contribution, SIMT
            float sv0[E], sv1[E];
            const float* sp = g_S + ((size_t)t * B + b0) * E;
#pragma unroll
            for (int e = 0; e < E; e++) { sv0[e] = sp[e]; sv1[e] = sp[8 * E + e]; }
#pragma unroll
            for (int nt = 0; nt < 4; nt++) {
                const float* wA = w0sm + (nt * 8 + c2) * E;
                const float* wB = wA + E;
#pragma unroll
                for (int e = 0; e < E; e++) {
                    acc[nt][0] += sv0[e] * wA[e];
                    acc[nt][1] += sv0[e] * wB[e];
                    acc[nt][2] += sv1[e] * wA[e];
                    acc[nt][3] += sv1[e] * wB[e];
                }
            }
        }

        const int wp = t & 1;
        __nv_bfloat16* Ohi = g_Hhi + ((size_t)(l * 2 + wp) * B) * H;
        __nv_bfloat16* Olo = g_Hlo + ((size_t)(l * 2 + wp) * B) * H;
        float hv[4];
#pragma unroll
        for (int rg = 0; rg < 4; rg++) {
            float iv = fsig(acc[0][rg]);
            float fv = fsig(acc[1][rg]);
            float gv = ftanh(acc[2][rg]);
            float ov = fsig(acc[3][rg]);
            float cv = fv * cst[rg] + iv * gv;
            cst[rg] = cv;
            hv[rg] = ov * ftanh(cv);
        }
#pragma unroll
        for (int half = 0; half < 2; half++) {
            float h0v = hv[half * 2], h1v = hv[half * 2 + 1];
            int row = b0 + half * 8;
            __nv_bfloat16 hh0 = __float2bfloat16(h0v);
            __nv_bfloat16 hh1 = __float2bfloat16(h1v);
            *(unsigned*)(Ohi + (size_t)row * H + jp0) = pk(hh0, hh1);
            *(unsigned*)(Olo + (size_t)row * H + jp0) =
                pk(__float2bfloat16(h0v - __bfloat162float(hh0)),
                   __float2bfloat16(h1v - __bfloat162float(hh1)));
            if (t == S - 1) {
                float2 o2 = make_float2(h0v, h1v);
                *(float2*)(out + (size_t)row * G4 + l * H + jj0) = o2;
            }
        }

        __threadfence();
        __syncthreads();
        if (tid == 0) atomicAdd(&g_cnt[l], 1);
    }
}

// ---------------- launch ----------------
extern "C" void kernel_launch(void* const* d_in, const int* in_sizes, int n_in,
                              void* d_out, int out_size) {
    const int*   x    = (const int*)d_in[0];
    const float* e01  = (const float*)d_in[1];
    const float* p01  = (const float*)d_in[2];
    const float* f01w = (const float*)d_in[3];
    const float* f01b = (const float*)d_in[4];
    const float* f02w = (const float*)d_in[5];
    const float* f02b = (const float*)d_in[6];
    const float* f03w = (const float*)d_in[7];
    const float* f03b = (const float*)d_in[8];
    const float* Wih0 = (const float*)d_in[9];
    const float* Wihr = (const float*)d_in[10];
    const float* Whh  = (const float*)d_in[11];
    const float* bih  = (const float*)d_in[12];
    const float* bhh  = (const float*)d_in[13];
    float* out = (float*)d_out;

    k_prep<<<(4 * 32 * 32 * 4 * 32 + 4096 + 10240 + 255) / 256, 256>>>(Wih0, Wihr, Whh, bih, bhh);
    k_embed<<<(S * B + 255) / 256, 256>>>(x, e01, p01, f01w, f01b);
    k_ssum_init<<<B, 256>>>(f02w, f02b, f03w, f03b);

    const int smem_bytes = 4096 * 16 + (32 + 320) * 4;  // 66944
    cudaFuncSetAttribute(lstm_rec, cudaFuncAttributeMaxDynamicSharedMemorySize,
                         smem_bytes);
    lstm_rec<<<NBLK, 256, smem_bytes>>>(out);
}

// round 5
// speedup vs baseline: 1.9667x; 1.3444x over previous
#include <cuda_runtime.h>
#include <cuda_bf16.h>
#include <math.h>

#define S 1024
#define B 128
#define E 10
#define H 256
#define L 4
#define G4 1024           // 4*H
#define NBPL 32           // blocks per layer
#define NBLK (NBPL * L)   // 128 persistent blocks

// ---------------- device scratch (static; no allocations) ----------------
// weight fragments: [l][nb][kt][nt][lane] = uint4(whi.x, whi.y, wlo.x, wlo.y)
__device__ __align__(16) uint4  g_Wp[4 * 32 * 32 * 4 * 32];
__device__ float  g_bias[4 * 32 * 32];
__device__ float  g_w0p[32 * 32 * 10];
__device__ float  g_S[S * B * E];
__device__ float  g_C0[L * B * H];
// h state: [l][slot(3)][b][64 uint4], row = 64 x uint4; unit u64 = (hi(j),hi(j+1),lo(j),lo(j+1))
__device__ __align__(16) uint4 g_Hq[L * 3 * B * 64];
__device__ int g_cnt[L * 8];   // per (layer, warp) completed-step counters (x32 blocks)

// ---------------- helpers ----------------
// perm-unit index for even col j: u64-unit within row
__device__ __host__ __forceinline__ int unitj(int j) {
    return (j >> 4) * 8 + (((j & 6) >> 1) << 1) + ((j >> 3) & 1);
}

__device__ __forceinline__ unsigned pk(__nv_bfloat16 a, __nv_bfloat16 b) {
    __nv_bfloat162 t; t.x = a; t.y = b;
    return *reinterpret_cast<unsigned*>(&t);
}

__device__ __forceinline__ void mma16816(float c[4], const unsigned a[4],
                                         unsigned b0, unsigned b1) {
    asm volatile(
        "mma.sync.aligned.m16n8k16.row.col.f32.bf16.bf16.f32 "
        "{%0,%1,%2,%3},{%4,%5,%6,%7},{%8,%9},{%0,%1,%2,%3};"
        : "+f"(c[0]), "+f"(c[1]), "+f"(c[2]), "+f"(c[3])
        : "r"(a[0]), "r"(a[1]), "r"(a[2]), "r"(a[3]), "r"(b0), "r"(b1));
}

__device__ __forceinline__ float fsig(float x) {
    return __fdividef(1.0f, 1.0f + __expf(-x));
}
__device__ __forceinline__ float ftanh(float x) {
    return 1.0f - __fdividef(2.0f, __expf(2.0f * x) + 1.0f);
}

__device__ __forceinline__ int ld_acq(const int* p) {
    int v;
    asm volatile("ld.acquire.gpu.global.b32 %0, [%1];" : "=r"(v) : "l"(p) : "memory");
    return v;
}
__device__ __forceinline__ void red_rel(int* p, int v) {
    asm volatile("red.release.gpu.global.add.s32 [%0], %1;" :: "l"(p), "r"(v) : "memory");
}

// one 16-kt half of the K sweep; Hq = per-lane activation ptr (kt=0), Wq = per-lane smem ptr (kt=0)
__device__ __forceinline__ void do_half(const uint4* __restrict__ Hq,
                                        const uint4* __restrict__ Wq,
                                        float acc[4][4]) {
#pragma unroll
    for (int kt = 0; kt < 16; ++kt) {
        uint4 u1 = __ldcg(Hq + kt * 4);
        uint4 u2 = __ldcg(Hq + kt * 4 + 8 * 64);
        unsigned a[4]  = {u1.x, u2.x, u1.z, u2.z};
        unsigned al[4] = {u1.y, u2.y, u1.w, u2.w};
        uint4 w0 = Wq[kt * 128 + 0];
        uint4 w1 = Wq[kt * 128 + 32];
        uint4 w2 = Wq[kt * 128 + 64];
        uint4 w3 = Wq[kt * 128 + 96];
        mma16816(acc[0], a,  w0.x, w0.y);
        mma16816(acc[1], a,  w1.x, w1.y);
        mma16816(acc[2], a,  w2.x, w2.y);
        mma16816(acc[3], a,  w3.x, w3.y);
        mma16816(acc[0], al, w0.x, w0.y);
        mma16816(acc[1], al, w1.x, w1.y);
        mma16816(acc[2], al, w2.x, w2.y);
        mma16816(acc[3], al, w3.x, w3.y);
        mma16816(acc[0], a,  w0.z, w0.w);
        mma16816(acc[1], a,  w1.z, w1.w);
        mma16816(acc[2], a,  w2.z, w2.w);
        mma16816(acc[3], a,  w3.z, w3.w);
    }
}

// ---------------- prep 1: pack weights + biases + layer0 Wih ----------------
__global__ void k_prep(const float* __restrict__ Wih0, const float* __restrict__ Wihr,
                       const float* __restrict__ Whh,  const float* __restrict__ bih,
                       const float* __restrict__ bhh) {
    int idx = blockIdx.x * 256 + threadIdx.x;
    if (idx < 4 * 32 * 32 * 4 * 32) {
        int lane = idx & 31;
        int nt   = (idx >> 5) & 3;
        int kt   = (idx >> 7) & 31;
        int nb   = (idx >> 12) & 31;
        int l    = idx >> 17;
        if (l == 0 && kt >= 16) return;
        int ncol = lane >> 2;
        int r    = nt * 256 + nb * 8 + ncol;
        int k0   = kt * 16 + (lane & 3) * 2;
        __nv_bfloat16 hi[4], lo[4];
#pragma unroll
        for (int q = 0; q < 4; q++) {
            int k = k0 + (q >> 1) * 8 + (q & 1);   // k0,k0+1,k0+8,k0+9
            float w;
            if (l == 0)       w = Whh[(size_t)r * H + k];
            else if (k < H)   w = Wihr[(size_t)((l - 1) * G4 + r) * H + k];
            else              w = Whh[(size_t)(l * G4 + r) * H + (k - H)];
            hi[q] = __float2bfloat16(w);
            lo[q] = __float2bfloat16(w - __bfloat162float(hi[q]));
        }
        g_Wp[idx] = make_uint4(pk(hi[0], hi[1]), pk(hi[2], hi[3]),
                               pk(lo[0], lo[1]), pk(lo[2], lo[3]));
    } else {
        int j = idx - 4 * 32 * 32 * 4 * 32;
        if (j < 4096) {
            int l = j >> 10, nb = (j >> 5) & 31, nl = j & 31;
            int r = (nl >> 3) * 256 + nb * 8 + (nl & 7);
            g_bias[j] = bih[l * G4 + r] + bhh[l * G4 + r];
        } else if (j < 4096 + 10240) {
            int jj = j - 4096;
            int nb = jj / 320, rem = jj % 320, nl = rem / 10, e = rem % 10;
            int r = (nl >> 3) * 256 + nb * 8 + (nl & 7);
            g_w0p[jj] = Wih0[r * E + e];
        }
    }
}

// ---------------- prep 2: s = relu((e01[x]+p01) @ f01_w.T + f01_b) ----------------
__global__ void k_embed(const int* __restrict__ x, const float* __restrict__ e01,
                        const float* __restrict__ p01, const float* __restrict__ f01w,
                        const float* __restrict__ f01b) {
    int idx = blockIdx.x * 256 + threadIdx.x;
    if (idx >= S * B) return;
    int t = idx / B;
    int tok = x[idx];
    float v[E];
#pragma unroll
    for (int e = 0; e < E; e++) v[e] = e01[tok * E + e] + p01[t * E + e];
    float* so = g_S + (size_t)idx * E;
#pragma unroll
    for (int i = 0; i < E; i++) {
        float a = f01b[i];
#pragma unroll
        for (int e = 0; e < E; e++) a += v[e] * f01w[i * E + e];
        so[i] = fmaxf(a, 0.0f);
    }
}

// ---------------- prep 3: ssum + h0/c0 + counter reset (fused) ----------------
__global__ void k_ssum_init(const float* __restrict__ f02w, const float* __restrict__ f02b,
                            const float* __restrict__ f03w, const float* __restrict__ f03b) {
    __shared__ float red[256 * E];
    __shared__ float ss[E];
    int b = blockIdx.x, tid = threadIdx.x;
    float acc[E];
#pragma unroll
    for (int e = 0; e < E; e++) acc[e] = 0.0f;
    for (int t = tid; t < S; t += 256) {
        const float* sp = g_S + ((size_t)t * B + b) * E;
#pragma unroll
        for (int e = 0; e < E; e++) acc[e] += sp[e];
    }
#pragma unroll
    for (int e = 0; e < E; e++) red[tid * E + e] = acc[e];
    __syncthreads();
    for (int s = 128; s > 0; s >>= 1) {
        if (tid < s) {
#pragma unroll
            for (int e = 0; e < E; e++) red[tid * E + e] += red[(tid + s) * E + e];
        }
        __syncthreads();
    }
    if (tid < E) ss[tid] = red[tid];
    if (b == 0 && tid < L * 8) g_cnt[tid] = 0;
    __syncthreads();
    __nv_bfloat16* Hb = (__nv_bfloat16*)g_Hq;
#pragma unroll
    for (int i = 0; i < 4; i++) {
        int r = tid + i * 256;           // gate row 0..1023
        float ah = f02b[r], ac = f03b[r];
#pragma unroll
        for (int e = 0; e < E; e++) {
            ah += ss[e] * f02w[r * E + e];
            ac += ss[e] * f03w[r * E + e];
        }
        ah = fmaxf(ah, 0.0f);
        ac = fmaxf(ac, 0.0f);
        int l = r >> 8, j = r & 255;
        int u = unitj(j & ~1);
        // initial h = "step -1" output -> slot 2
        size_t base = (((size_t)(l * 3 + 2) * B) + b) * 512 + u * 4 + (j & 1);
        __nv_bfloat16 hh = __float2bfloat16(ah);
        Hb[base]     = hh;
        Hb[base + 2] = __float2bfloat16(ah - __bfloat162float(hh));
        g_C0[((size_t)l * B + b) * H + j] = ac;
    }
}

// ---------------- persistent recurrent kernel: per-warp decoupled pipeline ----------------
__global__ void __launch_bounds__(256, 1) lstm_rec(float* __restrict__ out) {
    const int bid = blockIdx.x;
    const int l   = bid >> 5;
    const int nb  = bid & 31;
    const int tid = threadIdx.x;
    const int warp = tid >> 5;
    const int lane = tid & 31;

    extern __shared__ unsigned char smem[];
    uint4* Wsm  = (uint4*)smem;                 // [32][4][32] uint4 = 64KB
    float* bsm  = (float*)(Wsm + 4096);         // 32
    float* w0sm = bsm + 32;                     // 320 (layer 0 only)

    const int Kkt = (l == 0) ? 16 : 32;
    {
        const uint4* src = g_Wp + (size_t)(l * 32 + nb) * 4096;
        for (int i = tid; i < Kkt * 128; i += 256) Wsm[i] = src[i];
        if (tid < 32) bsm[tid] = g_bias[(l * 32 + nb) * 32 + tid];
        if (l == 0) for (int i = tid; i < 320; i += 256) w0sm[i] = g_w0p[nb * 320 + i];
    }

    const int qd  = lane & 3;
    const int r0  = lane >> 2;
    const int c2  = qd * 2;
    const int b0  = warp * 16 + r0;
    const int jj0 = nb * 8 + c2;
    const int ust = unitj(jj0);                 // store unit within row

    float cst[4];
    cst[0] = g_C0[((size_t)l * B + b0) * H + jj0];
    cst[1] = g_C0[((size_t)l * B + b0) * H + jj0 + 1];
    cst[2] = g_C0[((size_t)l * B + b0 + 8) * H + jj0];
    cst[3] = g_C0[((size_t)l * B + b0 + 8) * H + jj0 + 1];
    __syncthreads();

    // per-lane smem weight pointers
    const uint4* WqIn  = Wsm + lane;                       // input half (l>0): kt 0..15
    const uint4* WqOwn = Wsm + (l ? 16 * 128 : 0) + lane;  // Whh half

    int* cOwn = &g_cnt[l * 8 + warp];
    int* cIn  = (l > 0) ? &g_cnt[(l - 1) * 8 + warp] : nullptr;
    int* cDn  = (l < 3) ? &g_cnt[(l + 1) * 8 + warp] : nullptr;

    // slot bases (uint4 index): slot s of layer l at (l*3+s)*B*64
    const size_t laneOfs = (size_t)b0 * 64 + qd;
    int scur = 0, sprev = 2;

    float bias_r[4][2];
#pragma unroll
    for (int nt = 0; nt < 4; nt++) {
        bias_r[nt][0] = bsm[nt * 8 + c2];
        bias_r[nt][1] = bsm[nt * 8 + c2 + 1];
    }

    for (int t = 0; t < S; ++t) {
        float acc[4][4];
#pragma unroll
        for (int nt = 0; nt < 4; nt++) {
#pragma unroll
            for (int rg = 0; rg < 4; rg++)
                acc[nt][rg] = bias_r[nt][rg & 1];
        }

        if (l == 0) {  // E=10 input contribution (independent of all counters)
            float sv0[E], sv1[E];
            const float* sp = g_S + ((size_t)t * B + b0) * E;
#pragma unroll
            for (int e = 0; e < E; e++) { sv0[e] = sp[e]; sv1[e] = sp[8 * E + e]; }
#pragma unroll
            for (int nt = 0; nt < 4; nt++) {
                const float* wA = w0sm + (nt * 8 + c2) * E;
                const float* wB = wA + E;
#pragma unroll
                for (int e = 0; e < E; e++) {
                    acc[nt][0] += sv0[e] * wA[e];
                    acc[nt][1] += sv0[e] * wB[e];
                    acc[nt][2] += sv1[e] * wA[e];
                    acc[nt][3] += sv1[e] * wB[e];
                }
            }
        }

        // wait: own layer step t-1 done by all 32 blocks (warp lane-uniform poll)
        if (t > 0)           while (ld_acq(cOwn) < 32 * t) { }
        // anti-overwrite: layer below consumed h[t-3]
        if (l < 3 && t >= 3) while (ld_acq(cDn) < 32 * (t - 2)) { }

        // Whh half (own h from step t-1, slot sprev)
        do_half(g_Hq + (size_t)(l * 3 + sprev) * B * 64 + laneOfs, WqOwn, acc);

        // input half (layer l-1 h from step t, slot scur)
        if (l > 0) {
            while (ld_acq(cIn) < 32 * (t + 1)) { }
            do_half(g_Hq + (size_t)((l - 1) * 3 + scur) * B * 64 + laneOfs, WqIn, acc);
        }

        // epilogue
        float hv[4];
#pragma unroll
        for (int rg = 0; rg < 4; rg++) {
            float iv = fsig(acc[0][rg]);
            float fv = fsig(acc[1][rg]);
            float gv = ftanh(acc[2][rg]);
            float ov = fsig(acc[3][rg]);
            float cv = fv * cst[rg] + iv * gv;
            cst[rg] = cv;
            hv[rg] = ov * ftanh(cv);
        }

        unsigned long long* Ow =
            (unsigned long long*)(g_Hq + (size_t)(l * 3 + scur) * B * 64);
#pragma unroll
        for (int half = 0; half < 2; half++) {
            float h0v = hv[half * 2], h1v = hv[half * 2 + 1];
            int row = b0 + half * 8;
            __nv_bfloat16 hh0 = __float2bfloat16(h0v);
            __nv_bfloat16 hh1 = __float2bfloat16(h1v);
            unsigned lo32 = pk(hh0, hh1);
            unsigned hi32 = pk(__float2bfloat16(h0v - __bfloat162float(hh0)),
                               __float2bfloat16(h1v - __bfloat162float(hh1)));
            unsigned long long val = (unsigned long long)lo32 |
                                     ((unsigned long long)hi32 << 32);
            Ow[(size_t)row * 128 + ust] = val;
            if (t == S - 1) {
                float2 o2 = make_float2(h0v, h1v);
                *(float2*)(out + (size_t)row * G4 + l * H + jj0) = o2;
            }
        }

        __syncwarp();
        if (lane == 0) red_rel(cOwn, 1);

        sprev = scur;
        scur = (scur == 2) ? 0 : scur + 1;
    }
}

// ---------------- launch ----------------
extern "C" void kernel_launch(void* const* d_in, const int* in_sizes, int n_in,
                              void* d_out, int out_size) {
    const int*   x    = (const int*)d_in[0];
    const float* e01  = (const float*)d_in[1];
    const float* p01  = (const float*)d_in[2];
    const float* f01w = (const float*)d_in[3];
    const float* f01b = (const float*)d_in[4];
    const float* f02w = (const float*)d_in[5];
    const float* f02b = (const float*)d_in[6];
    const float* f03w = (const float*)d_in[7];
    const float* f03b = (const float*)d_in[8];
    const float* Wih0 = (const float*)d_in[9];
    const float* Wihr = (const float*)d_in[10];
    const float* Whh  = (const float*)d_in[11];
    const float* bih  = (const float*)d_in[12];
    const float* bhh  = (const float*)d_in[13];
    float* out = (float*)d_out;

    k_prep<<<(4 * 32 * 32 * 4 * 32 + 4096 + 10240 + 255) / 256, 256>>>(Wih0, Wihr, Whh, bih, bhh);
    k_embed<<<(S * B + 255) / 256, 256>>>(x, e01, p01, f01w, f01b);
    k_ssum_init<<<B, 256>>>(f02w, f02b, f03w, f03b);

    const int smem_bytes = 4096 * 16 + (32 + 320) * 4;  // 66944
    cudaFuncSetAttribute(lstm_rec, cudaFuncAttributeMaxDynamicSharedMemorySize,
                         smem_bytes);
    lstm_rec<<<NBLK, 256, smem_bytes>>>(out);
}